// round 15
// baseline (speedup 1.0000x reference)
#include <cuda_runtime.h>
#include <cuda_fp16.h>
#include <stdint.h>

#define E_    8
#define NTOK  4096
#define D_    768
#define H_    2048
#define CAP_  614          // int(1.2 * 4096 / 8)
#define SLOTS 1280         // padded >= 2*CAP_ = 1228
#define BM 128
#define BK 32
#define SA 40              // A smem row stride (halves): 80B rows, conflict-free ldmatrix
#define SB 136             // B smem row stride (halves): 272B rows
#define STAGES 4
#define A_ST (BM * SA)     // 5120
#define B_ST (BK * SB)     // 4352
#define SMEM_BYTES (STAGES * (A_ST + B_ST) * 2)   // 75776
#define NSM   148
#define PERSIST (2 * NSM)  // 296 CTAs, 2/SM

// ---------------- device scratch (allocation-free rule: __device__ globals) ---------
__device__ __align__(16) __half g_xh [NTOK * D_];
__device__ __align__(16) __half g_w1h[E_ * D_ * 2 * H_];
__device__ __align__(16) __half g_w2h[E_ * H_ * D_];
__device__ __align__(16) __half g_act[E_ * SLOTS * H_];
__device__ int   g_eid[NTOK * 2];
__device__ float g_wgt[NTOK * 2];
__device__ int   g_tok[E_ * SLOTS];
__device__ float g_wsl[E_ * SLOTS];
__device__ int   g_cnt[E_];

// ---------------- small helpers ----------------
__device__ __forceinline__ void cp16(__half* dst, const __half* src, bool p) {
    uint32_t d = (uint32_t)__cvta_generic_to_shared(dst);
    int sz = p ? 16 : 0;
    asm volatile("cp.async.cg.shared.global [%0], [%1], 16, %2;\n" :: "r"(d), "l"(src), "r"(sz));
}
__device__ __forceinline__ void cp_commit() { asm volatile("cp.async.commit_group;\n" ::: "memory"); }
__device__ __forceinline__ void cp_wait2()  { asm volatile("cp.async.wait_group 2;\n" ::: "memory"); }
__device__ __forceinline__ void cp_wait0()  { asm volatile("cp.async.wait_group 0;\n" ::: "memory"); }
__device__ __forceinline__ void ldsm4(uint32_t& r0, uint32_t& r1, uint32_t& r2, uint32_t& r3,
                                      const __half* p) {
    uint32_t a = (uint32_t)__cvta_generic_to_shared(p);
    asm volatile("ldmatrix.sync.aligned.m8n8.x4.shared.b16 {%0,%1,%2,%3}, [%4];\n"
                 : "=r"(r0), "=r"(r1), "=r"(r2), "=r"(r3) : "r"(a));
}
__device__ __forceinline__ void ldsm4t(uint32_t& r0, uint32_t& r1, uint32_t& r2, uint32_t& r3,
                                       const __half* p) {
    uint32_t a = (uint32_t)__cvta_generic_to_shared(p);
    asm volatile("ldmatrix.sync.aligned.m8n8.x4.trans.shared.b16 {%0,%1,%2,%3}, [%4];\n"
                 : "=r"(r0), "=r"(r1), "=r"(r2), "=r"(r3) : "r"(a));
}
__device__ __forceinline__ void mma16816(float c[4], const uint32_t a[4], uint32_t b0, uint32_t b1) {
    asm volatile("mma.sync.aligned.m16n8k16.row.col.f32.f16.f16.f32 "
                 "{%0,%1,%2,%3}, {%4,%5,%6,%7}, {%8,%9}, {%0,%1,%2,%3};\n"
                 : "+f"(c[0]), "+f"(c[1]), "+f"(c[2]), "+f"(c[3])
                 : "r"(a[0]), "r"(a[1]), "r"(a[2]), "r"(a[3]), "r"(b0), "r"(b1));
}
__device__ __forceinline__ void redadd2(float* p, float a, float b) {
    asm volatile("red.global.add.v2.f32 [%0], {%1, %2};" :: "l"(p), "f"(a), "f"(b) : "memory");
}

// ---------------- fp32 -> fp16 convert helper ----------------
__device__ __forceinline__ void cvt4(const float* __restrict__ s, __half* d, int i) {
    float4 v = ((const float4*)s)[i];
    ((__half2*)d)[2*i]   = __floats2half2_rn(v.x, v.y);
    ((__half2*)d)[2*i+1] = __floats2half2_rn(v.z, v.w);
}
#define N1_CHUNKS (E_*D_*2*H_/4)
#define N2_CHUNKS (E_*H_*D_/4)
#define CVT2_TILES 32
#define CVT2_Q (N2_CHUNKS / CVT2_TILES)   // 98304 chunks per cvt tile

// ------- gating (+ fused x fp32->fp16 convert): smem-transposed Wg, warp per token -------
__global__ __launch_bounds__(256) void gate_kernel(const float* __restrict__ x,
                                                   const float* __restrict__ wg) {
    __shared__ float swg[E_ * D_];          // transposed [e][d], 24KB
    int tid = threadIdx.x;
    for (int i = tid; i < D_ * E_ / 4; i += 256) {
        float4 v = ((const float4*)wg)[i];
        int d = i >> 1, eb = (i & 1) * 4;
        swg[(eb + 0) * D_ + d] = v.x;
        swg[(eb + 1) * D_ + d] = v.y;
        swg[(eb + 2) * D_ + d] = v.z;
        swg[(eb + 3) * D_ + d] = v.w;
    }
    __syncthreads();
    int wid = tid >> 5, lane = tid & 31;
    int tok = blockIdx.x * 8 + wid;
    const float4* x4 = (const float4*)(x + (size_t)tok * D_);
    __half2* xh2 = (__half2*)(g_xh + (size_t)tok * D_);
    float acc[E_];
#pragma unroll
    for (int e = 0; e < E_; e++) acc[e] = 0.f;
    for (int i = lane; i < D_ / 4; i += 32) {
        float4 v = x4[i];
        xh2[i*2]   = __floats2half2_rn(v.x, v.y);    // fused x convert
        xh2[i*2+1] = __floats2half2_rn(v.z, v.w);
#pragma unroll
        for (int e = 0; e < E_; e++) {
            float4 w4 = *(const float4*)&swg[e * D_ + i * 4];
            acc[e] += v.x * w4.x + v.y * w4.y + v.z * w4.z + v.w * w4.w;
        }
    }
#pragma unroll
    for (int e = 0; e < E_; e++) {
#pragma unroll
        for (int o = 16; o > 0; o >>= 1) acc[e] += __shfl_xor_sync(0xffffffffu, acc[e], o);
    }
    if (lane == 0) {
        int i0 = 0; float s0 = acc[0];
#pragma unroll
        for (int e = 1; e < E_; e++) if (acc[e] > s0) { s0 = acc[e]; i0 = e; }
        int i1 = -1; float s1 = -1e30f;
#pragma unroll
        for (int e = 0; e < E_; e++) if (e != i0 && acc[e] > s1) { s1 = acc[e]; i1 = e; }
        float ex  = expf(s1 - s0);
        float inv = 1.f / (1.f + ex);
        g_eid[tok*2]   = i0; g_eid[tok*2+1] = i1;
        g_wgt[tok*2]   = inv; g_wgt[tok*2+1] = ex * inv;
    }
}

// ------- routing (block 0) + W1 convert (blocks 1..): overlap assign's idle GPU -------
__global__ __launch_bounds__(1024) void assign_cvt_kernel(const float* __restrict__ w1) {
    if (blockIdx.x != 0) {
        int i = (blockIdx.x - 1) * 1024 + threadIdx.x;
        if (i < N1_CHUNKS) cvt4(w1, g_w1h, i);
        return;
    }
    __shared__ int wcnt[E_][32], woff[E_][32], ctot[E_], base[E_], kept0[E_];
    int tid = threadIdx.x, lane = tid & 31, wid = tid >> 5;
    for (int k = 0; k < 2; k++) {
        if (tid < E_) base[tid] = 0;
        __syncthreads();
        for (int it = 0; it < NTOK / 1024; it++) {
            int t = it * 1024 + tid;
            int e = g_eid[t*2 + k];
            int posw = 0;
#pragma unroll
            for (int ee = 0; ee < E_; ee++) {
                unsigned m = __ballot_sync(0xffffffffu, e == ee);
                if (e == ee)  posw = __popc(m & ((1u << lane) - 1));
                if (lane == ee) wcnt[ee][wid] = __popc(m);
            }
            __syncthreads();
            if (wid < E_) {
                int v = wcnt[wid][lane], s = v;
#pragma unroll
                for (int o = 1; o < 32; o <<= 1) { int n = __shfl_up_sync(0xffffffffu, s, o); if (lane >= o) s += n; }
                woff[wid][lane] = s - v;
                if (lane == 31) ctot[wid] = s;
            }
            __syncthreads();
            int p = base[e] + woff[e][wid] + posw;
            if (p < CAP_) {
                int slot = (k == 0) ? p : (kept0[e] + p);
                g_tok[e*SLOTS + slot] = t;
                g_wsl[e*SLOTS + slot] = g_wgt[t*2 + k];
            }
            __syncthreads();
            if (tid < E_) base[tid] += ctot[tid];
            __syncthreads();
        }
        if (tid < E_) {
            int kc = min(base[tid], CAP_);
            if (k == 0) kept0[tid] = kc;
            else        g_cnt[tid] = kept0[tid] + kc;
        }
        __syncthreads();
    }
}

// ---------------- GEMM1 (persistent): act = h1*silu(h2); first 32 tiles convert W2 ----------------
// Tiles: 0..31 = W2 convert slices; 32.. = gemm tiles (x 0..31, y 0..9, e 0..7).
__global__ __launch_bounds__(256, 2) void gemm1_kernel(const float* __restrict__ w2) {
    extern __shared__ __align__(16) __half sm[];
    const int tid  = threadIdx.x;
    const int lane = tid & 31, wid = tid >> 5;
    const int wm   = wid & 1,  wn  = wid >> 1;
    const int NT = CVT2_TILES + 32 * 10 * E_;   // 32 + 2560

    __shared__ int s_tok[BM];

    for (int t = blockIdx.x; t < NT; t += gridDim.x) {
        if (t < CVT2_TILES) {
            int base = t * CVT2_Q;
            for (int i = tid; i < CVT2_Q; i += 256) cvt4(w2, g_w2h, base + i);
            continue;
        }
        const int id = t - CVT2_TILES;
        const int e  = id >> 8;                 // / 320? no: 32*10=320 -> id/320
        // careful: tiles per expert = 320
        const int e2 = id / 320;
        const int rem = id - e2 * 320;
        const int y  = rem >> 5, xx = rem & 31;
        (void)e;
        const int cnt = g_cnt[e2];
        const int m0  = y * BM;
        if (m0 >= cnt) continue;
        const int a0  = xx * 64;

        __syncthreads();   // protect s_tok / smem reuse across tiles
        if (tid < BM) {
            int slot = m0 + tid;
            s_tok[tid] = (slot < cnt) ? g_tok[e2*SLOTS + slot] : -1;
        }
        __syncthreads();

        float acc[4][4][4];
#pragma unroll
        for (int i = 0; i < 4; i++)
#pragma unroll
            for (int j = 0; j < 4; j++)
#pragma unroll
                for (int q = 0; q < 4; q++) acc[i][j][q] = 0.f;

        const __half* w1base = g_w1h + (size_t)e2 * (D_ * 2 * H_);

        const int arow = tid >> 1, ag = (tid & 1) * 16;
        const int atok = s_tok[arow];
        const bool ap  = atok >= 0;
        const __half* a_src  = ap ? (g_xh + (size_t)atok * D_ + ag) : g_xh;
        __half*       a_dst0 = sm + arow * SA + ag;
        const int brow = tid >> 3, bcol = (tid & 7) * 16;
        const int bscol = (bcol < 64) ? (a0 + bcol) : (H_ + a0 + bcol - 64);
        const __half* b_src  = w1base + (size_t)brow * (2 * H_) + bscol;
        __half*       b_dst0 = sm + STAGES * A_ST + brow * SB + bcol;

        auto copy_stage = [&](int st, int kt) {
            const __half* as = a_src + kt * BK;
            cp16(a_dst0 + st * A_ST,     as,     ap);
            cp16(a_dst0 + st * A_ST + 8, as + 8, ap);
            const __half* bs = b_src + (size_t)kt * BK * (2 * H_);
            cp16(b_dst0 + st * B_ST,     bs,     true);
            cp16(b_dst0 + st * B_ST + 8, bs + 8, true);
        };
        auto compute_stage = [&](const __half* As, const __half* Bs) {
#pragma unroll
            for (int ks = 0; ks < 2; ks++) {
                int kk = ks * 16;
                uint32_t a[4][4];
#pragma unroll
                for (int mi = 0; mi < 4; mi++) {
                    const __half* p = As + (wm*64 + mi*16 + (lane & 15)) * SA + kk + (lane >> 4) * 8;
                    ldsm4(a[mi][0], a[mi][1], a[mi][2], a[mi][3], p);
                }
                uint32_t b[2][4];
#pragma unroll
                for (int ni = 0; ni < 2; ni++) {
                    const __half* p = Bs + (kk + (lane & 15)) * SB + wn*32 + ni*16 + (lane >> 4) * 8;
                    ldsm4t(b[ni][0], b[ni][1], b[ni][2], b[ni][3], p);
                }
#pragma unroll
                for (int mi = 0; mi < 4; mi++) {
                    mma16816(acc[mi][0], a[mi], b[0][0], b[0][1]);
                    mma16816(acc[mi][1], a[mi], b[0][2], b[0][3]);
                    mma16816(acc[mi][2], a[mi], b[1][0], b[1][1]);
                    mma16816(acc[mi][3], a[mi], b[1][2], b[1][3]);
                }
            }
        };

        const int KT = D_ / BK;  // 24
        copy_stage(0, 0); cp_commit();
        copy_stage(1, 1); cp_commit();
        copy_stage(2, 2); cp_commit();
        for (int kt = 0; kt < KT; ++kt) {
            cp_wait2();
            __syncthreads();
            if (kt + 3 < KT) copy_stage((kt + 3) % STAGES, kt + 3);
            cp_commit();
            compute_stage(sm + (kt % STAGES) * A_ST, sm + STAGES * A_ST + (kt % STAGES) * B_ST);
        }
        cp_wait0();
        __syncthreads();

        // epilogue: pair h1 (cols 0-63) with h2 (cols 64-127) via smem
        __half* hbuf = sm;
        __half* abuf = sm + 128 * 72;
        if (wn >= 2) {
            int cb = (wn - 2) * 32;
#pragma unroll
            for (int mi = 0; mi < 4; mi++) {
#pragma unroll
                for (int ni = 0; ni < 4; ni++) {
                    int r = wm*64 + mi*16 + (lane >> 2);
                    int c = cb + ni*8 + (lane & 3) * 2;
                    *(__half2*)&hbuf[r*72 + c]     = __floats2half2_rn(acc[mi][ni][0], acc[mi][ni][1]);
                    *(__half2*)&hbuf[(r+8)*72 + c] = __floats2half2_rn(acc[mi][ni][2], acc[mi][ni][3]);
                }
            }
        }
        __syncthreads();
        if (wn < 2) {
            int cb = wn * 32;
#pragma unroll
            for (int mi = 0; mi < 4; mi++) {
#pragma unroll
                for (int ni = 0; ni < 4; ni++) {
                    int r = wm*64 + mi*16 + (lane >> 2);
                    int c = cb + ni*8 + (lane & 3) * 2;
                    float g0 = __half2float(hbuf[r*72 + c]);
                    float g1 = __half2float(hbuf[r*72 + c + 1]);
                    float g2 = __half2float(hbuf[(r+8)*72 + c]);
                    float g3 = __half2float(hbuf[(r+8)*72 + c + 1]);
                    float a0v = acc[mi][ni][0] * g0 * (1.f / (1.f + __expf(-g0)));
                    float a1v = acc[mi][ni][1] * g1 * (1.f / (1.f + __expf(-g1)));
                    float a2v = acc[mi][ni][2] * g2 * (1.f / (1.f + __expf(-g2)));
                    float a3v = acc[mi][ni][3] * g3 * (1.f / (1.f + __expf(-g3)));
                    *(__half2*)&abuf[r*72 + c]     = __floats2half2_rn(a0v, a1v);
                    *(__half2*)&abuf[(r+8)*72 + c] = __floats2half2_rn(a2v, a3v);
                }
            }
        }
        __syncthreads();
        for (int i = tid; i < 128 * 8; i += 256) {
            int r = i >> 3, g = i & 7;
            if (m0 + r < cnt)
                *(float4*)(&g_act[(size_t)(e2*SLOTS + m0 + r) * H_ + a0 + g*8]) =
                    *(float4*)(&abuf[r*72 + g*8]);
        }
        __syncthreads();
    }
}

// ---------------- GEMM2 (persistent): out[tok] += w * (act @ W2[e]) ----------------
// Tiles: x 0..5, y 0..9, e 0..7 -> 480 tiles.
__global__ __launch_bounds__(256, 2) void gemm2_kernel(float* __restrict__ out) {
    extern __shared__ __align__(16) __half sm[];
    const int tid  = threadIdx.x;
    const int lane = tid & 31, wid = tid >> 5;
    const int wm   = wid & 1,  wn  = wid >> 1;
    const int NT = 6 * 10 * E_;   // 480

    __shared__ int   s_tok[BM];
    __shared__ float s_w[BM];

    for (int t = blockIdx.x; t < NT; t += gridDim.x) {
        const int e   = t / 60;
        const int rem = t - e * 60;
        const int y   = rem / 6, xx = rem - y * 6;
        const int cnt = g_cnt[e];
        const int m0  = y * BM;
        if (m0 >= cnt) continue;
        const int n0  = xx * 128;

        __syncthreads();
        if (tid < BM) {
            int slot = m0 + tid;
            bool v = slot < cnt;
            s_tok[tid] = v ? g_tok[e*SLOTS + slot] : -1;
            s_w[tid]   = v ? g_wsl[e*SLOTS + slot] : 0.f;
        }
        __syncthreads();

        float acc[4][4][4];
#pragma unroll
        for (int i = 0; i < 4; i++)
#pragma unroll
            for (int j = 0; j < 4; j++)
#pragma unroll
                for (int q = 0; q < 4; q++) acc[i][j][q] = 0.f;

        const __half* w2base = g_w2h + (size_t)e * (H_ * D_);
        const __half* abase  = g_act + (size_t)e * SLOTS * H_;

        const int arow = tid >> 1, ag = (tid & 1) * 16;
        const bool ap  = (m0 + arow) < cnt;
        const __half* a_src  = ap ? (abase + (size_t)(m0 + arow) * H_ + ag) : abase;
        __half*       a_dst0 = sm + arow * SA + ag;
        const int brow = tid >> 3, bcol = (tid & 7) * 16;
        const __half* b_src  = w2base + (size_t)brow * D_ + n0 + bcol;
        __half*       b_dst0 = sm + STAGES * A_ST + brow * SB + bcol;

        auto copy_stage = [&](int st, int kt) {
            const __half* as = a_src + kt * BK;
            cp16(a_dst0 + st * A_ST,     as,     ap);
            cp16(a_dst0 + st * A_ST + 8, as + 8, ap);
            const __half* bs = b_src + (size_t)kt * BK * D_;
            cp16(b_dst0 + st * B_ST,     bs,     true);
            cp16(b_dst0 + st * B_ST + 8, bs + 8, true);
        };
        auto compute_stage = [&](const __half* As, const __half* Bs) {
#pragma unroll
            for (int ks = 0; ks < 2; ks++) {
                int kk = ks * 16;
                uint32_t a[4][4];
#pragma unroll
                for (int mi = 0; mi < 4; mi++) {
                    const __half* p = As + (wm*64 + mi*16 + (lane & 15)) * SA + kk + (lane >> 4) * 8;
                    ldsm4(a[mi][0], a[mi][1], a[mi][2], a[mi][3], p);
                }
                uint32_t b[2][4];
#pragma unroll
                for (int ni = 0; ni < 2; ni++) {
                    const __half* p = Bs + (kk + (lane & 15)) * SB + wn*32 + ni*16 + (lane >> 4) * 8;
                    ldsm4t(b[ni][0], b[ni][1], b[ni][2], b[ni][3], p);
                }
#pragma unroll
                for (int mi = 0; mi < 4; mi++) {
                    mma16816(acc[mi][0], a[mi], b[0][0], b[0][1]);
                    mma16816(acc[mi][1], a[mi], b[0][2], b[0][3]);
                    mma16816(acc[mi][2], a[mi], b[1][0], b[1][1]);
                    mma16816(acc[mi][3], a[mi], b[1][2], b[1][3]);
                }
            }
        };

        const int KT = H_ / BK;  // 64
        copy_stage(0, 0); cp_commit();
        copy_stage(1, 1); cp_commit();
        copy_stage(2, 2); cp_commit();
        for (int kt = 0; kt < KT; ++kt) {
            cp_wait2();
            __syncthreads();
            if (kt + 3 < KT) copy_stage((kt + 3) % STAGES, kt + 3);
            cp_commit();
            compute_stage(sm + (kt % STAGES) * A_ST, sm + STAGES * A_ST + (kt % STAGES) * B_ST);
        }
        cp_wait0();

        // epilogue: weighted scatter-add, paired v2 red
#pragma unroll
        for (int mi = 0; mi < 4; mi++) {
            int r = wm*64 + mi*16 + (lane >> 2);
#pragma unroll
            for (int hh = 0; hh < 2; hh++) {
                int rr = r + hh * 8;
                if (m0 + rr < cnt) {
                    int   tok = s_tok[rr];
                    float w   = s_w[rr];
#pragma unroll
                    for (int ni = 0; ni < 4; ni++) {
                        int c = n0 + wn*32 + ni*8 + (lane & 3) * 2;
                        redadd2(&out[(size_t)tok * D_ + c],
                                w * acc[mi][ni][hh*2 + 0], w * acc[mi][ni][hh*2 + 1]);
                    }
                }
            }
        }
        __syncthreads();
    }
}

// ---------------- launcher ----------------
// Launches: memset(1), gate(2), assign_cvt(3), gemm1(4), gemm2(5 <- ncu target).
extern "C" void kernel_launch(void* const* d_in, const int* in_sizes, int n_in,
                              void* d_out, int out_size) {
    (void)in_sizes; (void)n_in;
    const float* x  = (const float*)d_in[0];
    const float* wg = (const float*)d_in[1];
    const float* w1 = (const float*)d_in[2];
    const float* w2 = (const float*)d_in[3];
    float* out = (float*)d_out;

    cudaFuncSetAttribute(gemm1_kernel, cudaFuncAttributeMaxDynamicSharedMemorySize, SMEM_BYTES);
    cudaFuncSetAttribute(gemm2_kernel, cudaFuncAttributeMaxDynamicSharedMemorySize, SMEM_BYTES);

    cudaMemsetAsync(d_out, 0, (size_t)out_size * sizeof(float));
    gate_kernel<<<NTOK/8, 256>>>(x, wg);
    assign_cvt_kernel<<<1 + N1_CHUNKS/1024, 1024>>>(w1);
    gemm1_kernel<<<PERSIST, 256, SMEM_BYTES>>>(w2);
    gemm2_kernel<<<PERSIST, 256, SMEM_BYTES>>>(out);
}

// round 16
// speedup vs baseline: 1.1914x; 1.1914x over previous
#include <cuda_runtime.h>
#include <cuda_fp16.h>
#include <stdint.h>

#define E_    8
#define NTOK  4096
#define D_    768
#define H_    2048
#define CAP_  614          // int(1.2 * 4096 / 8)
#define SLOTS 1280         // padded >= 2*CAP_ = 1228
#define BM 128
#define BK 32
#define SA 40              // A smem row stride (halves): 80B rows, conflict-free ldmatrix
#define SB 136             // B smem row stride (halves): 272B rows
#define STAGES 4
#define A_ST (BM * SA)     // 5120
#define B_ST (BK * SB)     // 4352
#define SMEM_BYTES (STAGES * (A_ST + B_ST) * 2)   // 75776

// ---------------- device scratch (allocation-free rule: __device__ globals) ---------
__device__ __align__(16) __half g_xh [NTOK * D_];
__device__ __align__(16) __half g_w1h[E_ * D_ * 2 * H_];
__device__ __align__(16) __half g_w2h[E_ * H_ * D_];
__device__ __align__(16) __half g_act[E_ * SLOTS * H_];
__device__ int   g_eid[NTOK * 2];
__device__ float g_wgt[NTOK * 2];
__device__ int   g_tok[E_ * SLOTS];
__device__ float g_wsl[E_ * SLOTS];
__device__ int   g_cnt[E_];
__device__ int   g_done[E_];     // gemm1 tiles completed per expert
__device__ int   g_w2done;       // W2 convert tiles completed

// ---------------- small helpers ----------------
__device__ __forceinline__ void cp16(__half* dst, const __half* src, bool p) {
    uint32_t d = (uint32_t)__cvta_generic_to_shared(dst);
    int sz = p ? 16 : 0;
    asm volatile("cp.async.cg.shared.global [%0], [%1], 16, %2;\n" :: "r"(d), "l"(src), "r"(sz));
}
__device__ __forceinline__ void cp_commit() { asm volatile("cp.async.commit_group;\n" ::: "memory"); }
__device__ __forceinline__ void cp_wait2()  { asm volatile("cp.async.wait_group 2;\n" ::: "memory"); }
__device__ __forceinline__ void ldsm4(uint32_t& r0, uint32_t& r1, uint32_t& r2, uint32_t& r3,
                                      const __half* p) {
    uint32_t a = (uint32_t)__cvta_generic_to_shared(p);
    asm volatile("ldmatrix.sync.aligned.m8n8.x4.shared.b16 {%0,%1,%2,%3}, [%4];\n"
                 : "=r"(r0), "=r"(r1), "=r"(r2), "=r"(r3) : "r"(a));
}
__device__ __forceinline__ void ldsm4t(uint32_t& r0, uint32_t& r1, uint32_t& r2, uint32_t& r3,
                                       const __half* p) {
    uint32_t a = (uint32_t)__cvta_generic_to_shared(p);
    asm volatile("ldmatrix.sync.aligned.m8n8.x4.trans.shared.b16 {%0,%1,%2,%3}, [%4];\n"
                 : "=r"(r0), "=r"(r1), "=r"(r2), "=r"(r3) : "r"(a));
}
__device__ __forceinline__ void mma16816(float c[4], const uint32_t a[4], uint32_t b0, uint32_t b1) {
    asm volatile("mma.sync.aligned.m16n8k16.row.col.f32.f16.f16.f32 "
                 "{%0,%1,%2,%3}, {%4,%5,%6,%7}, {%8,%9}, {%0,%1,%2,%3};\n"
                 : "+f"(c[0]), "+f"(c[1]), "+f"(c[2]), "+f"(c[3])
                 : "r"(a[0]), "r"(a[1]), "r"(a[2]), "r"(a[3]), "r"(b0), "r"(b1));
}
__device__ __forceinline__ void redadd2(float* p, float a, float b) {
    asm volatile("red.global.add.v2.f32 [%0], {%1, %2};" :: "l"(p), "f"(a), "f"(b) : "memory");
}

// ---------------- fp32 -> fp16 convert helper ----------------
__device__ __forceinline__ void cvt4(const float* __restrict__ s, __half* d, int i) {
    float4 v = ((const float4*)s)[i];
    ((__half2*)d)[2*i]   = __floats2half2_rn(v.x, v.y);
    ((__half2*)d)[2*i+1] = __floats2half2_rn(v.z, v.w);
}
#define N1_CHUNKS (E_*D_*2*H_/4)
#define N2_CHUNKS (E_*H_*D_/4)
#define CVT2_TILES 32
#define CVT2_Q (N2_CHUNKS / CVT2_TILES)
#define G1_TILES (32 * 10 * E_)   // 2560
#define G2_TILES (6 * 10 * E_)    // 480

// ------- gating (+ fused x fp32->fp16 convert): smem-transposed Wg, warp per token -------
__global__ __launch_bounds__(256) void gate_kernel(const float* __restrict__ x,
                                                   const float* __restrict__ wg) {
    __shared__ float swg[E_ * D_];
    int tid = threadIdx.x;
    for (int i = tid; i < D_ * E_ / 4; i += 256) {
        float4 v = ((const float4*)wg)[i];
        int d = i >> 1, eb = (i & 1) * 4;
        swg[(eb + 0) * D_ + d] = v.x;
        swg[(eb + 1) * D_ + d] = v.y;
        swg[(eb + 2) * D_ + d] = v.z;
        swg[(eb + 3) * D_ + d] = v.w;
    }
    __syncthreads();
    int wid = tid >> 5, lane = tid & 31;
    int tok = blockIdx.x * 8 + wid;
    const float4* x4 = (const float4*)(x + (size_t)tok * D_);
    __half2* xh2 = (__half2*)(g_xh + (size_t)tok * D_);
    float acc[E_];
#pragma unroll
    for (int e = 0; e < E_; e++) acc[e] = 0.f;
    for (int i = lane; i < D_ / 4; i += 32) {
        float4 v = x4[i];
        xh2[i*2]   = __floats2half2_rn(v.x, v.y);
        xh2[i*2+1] = __floats2half2_rn(v.z, v.w);
#pragma unroll
        for (int e = 0; e < E_; e++) {
            float4 w4 = *(const float4*)&swg[e * D_ + i * 4];
            acc[e] += v.x * w4.x + v.y * w4.y + v.z * w4.z + v.w * w4.w;
        }
    }
#pragma unroll
    for (int e = 0; e < E_; e++) {
#pragma unroll
        for (int o = 16; o > 0; o >>= 1) acc[e] += __shfl_xor_sync(0xffffffffu, acc[e], o);
    }
    if (lane == 0) {
        int i0 = 0; float s0 = acc[0];
#pragma unroll
        for (int e = 1; e < E_; e++) if (acc[e] > s0) { s0 = acc[e]; i0 = e; }
        int i1 = -1; float s1 = -1e30f;
#pragma unroll
        for (int e = 0; e < E_; e++) if (e != i0 && acc[e] > s1) { s1 = acc[e]; i1 = e; }
        float ex  = expf(s1 - s0);
        float inv = 1.f / (1.f + ex);
        g_eid[tok*2]   = i0; g_eid[tok*2+1] = i1;
        g_wgt[tok*2]   = inv; g_wgt[tok*2+1] = ex * inv;
    }
}

// ------- routing (block 0, also zeroes sync counters) + W1 convert (blocks 1..) -------
__global__ __launch_bounds__(1024) void assign_cvt_kernel(const float* __restrict__ w1) {
    if (blockIdx.x != 0) {
        int i = (blockIdx.x - 1) * 1024 + threadIdx.x;
        if (i < N1_CHUNKS) cvt4(w1, g_w1h, i);
        return;
    }
    __shared__ int wcnt[E_][32], woff[E_][32], ctot[E_], base[E_], kept0[E_];
    int tid = threadIdx.x, lane = tid & 31, wid = tid >> 5;
    if (tid < E_) g_done[tid] = 0;
    if (tid == 0) g_w2done = 0;
    for (int k = 0; k < 2; k++) {
        if (tid < E_) base[tid] = 0;
        __syncthreads();
        for (int it = 0; it < NTOK / 1024; it++) {
            int t = it * 1024 + tid;
            int e = g_eid[t*2 + k];
            int posw = 0;
#pragma unroll
            for (int ee = 0; ee < E_; ee++) {
                unsigned m = __ballot_sync(0xffffffffu, e == ee);
                if (e == ee)  posw = __popc(m & ((1u << lane) - 1));
                if (lane == ee) wcnt[ee][wid] = __popc(m);
            }
            __syncthreads();
            if (wid < E_) {
                int v = wcnt[wid][lane], s = v;
#pragma unroll
                for (int o = 1; o < 32; o <<= 1) { int n = __shfl_up_sync(0xffffffffu, s, o); if (lane >= o) s += n; }
                woff[wid][lane] = s - v;
                if (lane == 31) ctot[wid] = s;
            }
            __syncthreads();
            int p = base[e] + woff[e][wid] + posw;
            if (p < CAP_) {
                int slot = (k == 0) ? p : (kept0[e] + p);
                g_tok[e*SLOTS + slot] = t;
                g_wsl[e*SLOTS + slot] = g_wgt[t*2 + k];
            }
            __syncthreads();
            if (tid < E_) base[tid] += ctot[tid];
            __syncthreads();
        }
        if (tid < E_) {
            int kc = min(base[tid], CAP_);
            if (k == 0) kept0[tid] = kc;
            else        g_cnt[tid] = kept0[tid] + kc;
        }
        __syncthreads();
    }
}

// =============== merged GEMM kernel: W2-cvt tiles | gemm1 tiles | gemm2 tiles ===============
// Block order: [0,32) W2 convert; [32, 32+2560) gemm1 (expert-major); [2592, 3072) gemm2.
// gemm2 tiles spin until their expert's gemm1 tiles and the W2 convert are published.
__global__ __launch_bounds__(256, 2) void moe_gemm_kernel(const float* __restrict__ w2,
                                                          float* __restrict__ out) {
    extern __shared__ __align__(16) __half sm[];
    const int tid  = threadIdx.x;
    const int lane = tid & 31, wid = tid >> 5;
    const int wm   = wid & 1,  wn  = wid >> 1;
    int b = blockIdx.x;

    __shared__ int   s_tok[BM];
    __shared__ float s_w[BM];

    // ---------- phase 0: W2 convert tiles ----------
    if (b < CVT2_TILES) {
        int base = b * CVT2_Q;
        for (int i = tid; i < CVT2_Q; i += 256) cvt4(w2, g_w2h, base + i);
        __threadfence();
        __syncthreads();
        if (tid == 0) atomicAdd(&g_w2done, 1);
        return;
    }
    b -= CVT2_TILES;

    // ---------- phase 1: gemm1 tiles ----------
    if (b < G1_TILES) {
        const int e   = b / 320;
        const int rem = b - e * 320;
        const int y   = rem >> 5, xx = rem & 31;
        const int cnt = g_cnt[e];
        const int m0  = y * BM;
        if (m0 >= cnt) { if (tid == 0) atomicAdd(&g_done[e], 1); return; }
        const int a0  = xx * 64;

        if (tid < BM) {
            int slot = m0 + tid;
            s_tok[tid] = (slot < cnt) ? g_tok[e*SLOTS + slot] : -1;
        }
        __syncthreads();

        float acc[4][4][4];
#pragma unroll
        for (int i = 0; i < 4; i++)
#pragma unroll
            for (int j = 0; j < 4; j++)
#pragma unroll
                for (int q = 0; q < 4; q++) acc[i][j][q] = 0.f;

        const __half* w1base = g_w1h + (size_t)e * (D_ * 2 * H_);

        const int arow = tid >> 1, ag = (tid & 1) * 16;
        const int atok = s_tok[arow];
        const bool ap  = atok >= 0;
        const __half* a_src  = ap ? (g_xh + (size_t)atok * D_ + ag) : g_xh;
        __half*       a_dst0 = sm + arow * SA + ag;
        const int brow = tid >> 3, bcol = (tid & 7) * 16;
        const int bscol = (bcol < 64) ? (a0 + bcol) : (H_ + a0 + bcol - 64);
        const __half* b_src  = w1base + (size_t)brow * (2 * H_) + bscol;
        __half*       b_dst0 = sm + STAGES * A_ST + brow * SB + bcol;

        auto copy_stage = [&](int st, int kt) {
            const __half* as = a_src + kt * BK;
            cp16(a_dst0 + st * A_ST,     as,     ap);
            cp16(a_dst0 + st * A_ST + 8, as + 8, ap);
            const __half* bs = b_src + (size_t)kt * BK * (2 * H_);
            cp16(b_dst0 + st * B_ST,     bs,     true);
            cp16(b_dst0 + st * B_ST + 8, bs + 8, true);
        };
        auto compute_stage = [&](const __half* As, const __half* Bs) {
#pragma unroll
            for (int ks = 0; ks < 2; ks++) {
                int kk = ks * 16;
                uint32_t a[4][4];
#pragma unroll
                for (int mi = 0; mi < 4; mi++) {
                    const __half* p = As + (wm*64 + mi*16 + (lane & 15)) * SA + kk + (lane >> 4) * 8;
                    ldsm4(a[mi][0], a[mi][1], a[mi][2], a[mi][3], p);
                }
                uint32_t bb[2][4];
#pragma unroll
                for (int ni = 0; ni < 2; ni++) {
                    const __half* p = Bs + (kk + (lane & 15)) * SB + wn*32 + ni*16 + (lane >> 4) * 8;
                    ldsm4t(bb[ni][0], bb[ni][1], bb[ni][2], bb[ni][3], p);
                }
#pragma unroll
                for (int mi = 0; mi < 4; mi++) {
                    mma16816(acc[mi][0], a[mi], bb[0][0], bb[0][1]);
                    mma16816(acc[mi][1], a[mi], bb[0][2], bb[0][3]);
                    mma16816(acc[mi][2], a[mi], bb[1][0], bb[1][1]);
                    mma16816(acc[mi][3], a[mi], bb[1][2], bb[1][3]);
                }
            }
        };

        const int KT = D_ / BK;  // 24
        copy_stage(0, 0); cp_commit();
        copy_stage(1, 1); cp_commit();
        copy_stage(2, 2); cp_commit();
        for (int kt = 0; kt < KT; ++kt) {
            cp_wait2();
            __syncthreads();
            if (kt + 3 < KT) copy_stage((kt + 3) % STAGES, kt + 3);
            cp_commit();
            compute_stage(sm + (kt % STAGES) * A_ST, sm + STAGES * A_ST + (kt % STAGES) * B_ST);
        }
        __syncthreads();

        __half* hbuf = sm;
        __half* abuf = sm + 128 * 72;
        if (wn >= 2) {
            int cb = (wn - 2) * 32;
#pragma unroll
            for (int mi = 0; mi < 4; mi++) {
#pragma unroll
                for (int ni = 0; ni < 4; ni++) {
                    int r = wm*64 + mi*16 + (lane >> 2);
                    int c = cb + ni*8 + (lane & 3) * 2;
                    *(__half2*)&hbuf[r*72 + c]     = __floats2half2_rn(acc[mi][ni][0], acc[mi][ni][1]);
                    *(__half2*)&hbuf[(r+8)*72 + c] = __floats2half2_rn(acc[mi][ni][2], acc[mi][ni][3]);
                }
            }
        }
        __syncthreads();
        if (wn < 2) {
            int cb = wn * 32;
#pragma unroll
            for (int mi = 0; mi < 4; mi++) {
#pragma unroll
                for (int ni = 0; ni < 4; ni++) {
                    int r = wm*64 + mi*16 + (lane >> 2);
                    int c = cb + ni*8 + (lane & 3) * 2;
                    float g0 = __half2float(hbuf[r*72 + c]);
                    float g1 = __half2float(hbuf[r*72 + c + 1]);
                    float g2 = __half2float(hbuf[(r+8)*72 + c]);
                    float g3 = __half2float(hbuf[(r+8)*72 + c + 1]);
                    float a0v = acc[mi][ni][0] * g0 * (1.f / (1.f + __expf(-g0)));
                    float a1v = acc[mi][ni][1] * g1 * (1.f / (1.f + __expf(-g1)));
                    float a2v = acc[mi][ni][2] * g2 * (1.f / (1.f + __expf(-g2)));
                    float a3v = acc[mi][ni][3] * g3 * (1.f / (1.f + __expf(-g3)));
                    *(__half2*)&abuf[r*72 + c]     = __floats2half2_rn(a0v, a1v);
                    *(__half2*)&abuf[(r+8)*72 + c] = __floats2half2_rn(a2v, a3v);
                }
            }
        }
        __syncthreads();
        for (int i = tid; i < 128 * 8; i += 256) {
            int r = i >> 3, g = i & 7;
            if (m0 + r < cnt)
                *(float4*)(&g_act[(size_t)(e*SLOTS + m0 + r) * H_ + a0 + g*8]) =
                    *(float4*)(&abuf[r*72 + g*8]);
        }
        // publish: all act stores visible, then count this tile
        __threadfence();
        __syncthreads();
        if (tid == 0) atomicAdd(&g_done[e], 1);
        return;
    }
    b -= G1_TILES;

    // ---------- phase 2: gemm2 tiles (wait for producer) ----------
    {
        const int e   = b / 60;
        const int rem = b - e * 60;
        const int y   = rem / 6, xx = rem - y * 6;

        if (tid == 0) {
            while (atomicAdd(&g_done[e], 0) < 320 || atomicAdd(&g_w2done, 0) < CVT2_TILES)
                __nanosleep(200);
        }
        __syncthreads();
        __threadfence();   // acquire: order subsequent reads after observed publishes

        const int cnt = g_cnt[e];
        const int m0  = y * BM;
        if (m0 >= cnt) return;
        const int n0  = xx * 128;

        if (tid < BM) {
            int slot = m0 + tid;
            bool v = slot < cnt;
            s_tok[tid] = v ? g_tok[e*SLOTS + slot] : -1;
            s_w[tid]   = v ? g_wsl[e*SLOTS + slot] : 0.f;
        }
        __syncthreads();

        float acc[4][4][4];
#pragma unroll
        for (int i = 0; i < 4; i++)
#pragma unroll
            for (int j = 0; j < 4; j++)
#pragma unroll
                for (int q = 0; q < 4; q++) acc[i][j][q] = 0.f;

        const __half* w2base = g_w2h + (size_t)e * (H_ * D_);
        const __half* abase  = g_act + (size_t)e * SLOTS * H_;

        const int arow = tid >> 1, ag = (tid & 1) * 16;
        const bool ap  = (m0 + arow) < cnt;
        const __half* a_src  = ap ? (abase + (size_t)(m0 + arow) * H_ + ag) : abase;
        __half*       a_dst0 = sm + arow * SA + ag;
        const int brow = tid >> 3, bcol = (tid & 7) * 16;
        const __half* b_src  = w2base + (size_t)brow * D_ + n0 + bcol;
        __half*       b_dst0 = sm + STAGES * A_ST + brow * SB + bcol;

        auto copy_stage = [&](int st, int kt) {
            const __half* as = a_src + kt * BK;
            cp16(a_dst0 + st * A_ST,     as,     ap);
            cp16(a_dst0 + st * A_ST + 8, as + 8, ap);
            const __half* bs = b_src + (size_t)kt * BK * D_;
            cp16(b_dst0 + st * B_ST,     bs,     true);
            cp16(b_dst0 + st * B_ST + 8, bs + 8, true);
        };
        auto compute_stage = [&](const __half* As, const __half* Bs) {
#pragma unroll
            for (int ks = 0; ks < 2; ks++) {
                int kk = ks * 16;
                uint32_t a[4][4];
#pragma unroll
                for (int mi = 0; mi < 4; mi++) {
                    const __half* p = As + (wm*64 + mi*16 + (lane & 15)) * SA + kk + (lane >> 4) * 8;
                    ldsm4(a[mi][0], a[mi][1], a[mi][2], a[mi][3], p);
                }
                uint32_t bb[2][4];
#pragma unroll
                for (int ni = 0; ni < 2; ni++) {
                    const __half* p = Bs + (kk + (lane & 15)) * SB + wn*32 + ni*16 + (lane >> 4) * 8;
                    ldsm4t(bb[ni][0], bb[ni][1], bb[ni][2], bb[ni][3], p);
                }
#pragma unroll
                for (int mi = 0; mi < 4; mi++) {
                    mma16816(acc[mi][0], a[mi], bb[0][0], bb[0][1]);
                    mma16816(acc[mi][1], a[mi], bb[0][2], bb[0][3]);
                    mma16816(acc[mi][2], a[mi], bb[1][0], bb[1][1]);
                    mma16816(acc[mi][3], a[mi], bb[1][2], bb[1][3]);
                }
            }
        };

        const int KT = H_ / BK;  // 64
        copy_stage(0, 0); cp_commit();
        copy_stage(1, 1); cp_commit();
        copy_stage(2, 2); cp_commit();
        for (int kt = 0; kt < KT; ++kt) {
            cp_wait2();
            __syncthreads();
            if (kt + 3 < KT) copy_stage((kt + 3) % STAGES, kt + 3);
            cp_commit();
            compute_stage(sm + (kt % STAGES) * A_ST, sm + STAGES * A_ST + (kt % STAGES) * B_ST);
        }

#pragma unroll
        for (int mi = 0; mi < 4; mi++) {
            int r = wm*64 + mi*16 + (lane >> 2);
#pragma unroll
            for (int hh = 0; hh < 2; hh++) {
                int rr = r + hh * 8;
                if (m0 + rr < cnt) {
                    int   tok = s_tok[rr];
                    float w   = s_w[rr];
#pragma unroll
                    for (int ni = 0; ni < 4; ni++) {
                        int c = n0 + wn*32 + ni*8 + (lane & 3) * 2;
                        redadd2(&out[(size_t)tok * D_ + c],
                                w * acc[mi][ni][hh*2 + 0], w * acc[mi][ni][hh*2 + 1]);
                    }
                }
            }
        }
    }
}

// ---------------- launcher ----------------
// Launches: memset(1), gate(2), assign_cvt(3), moe_gemm(4).
extern "C" void kernel_launch(void* const* d_in, const int* in_sizes, int n_in,
                              void* d_out, int out_size) {
    (void)in_sizes; (void)n_in;
    const float* x  = (const float*)d_in[0];
    const float* wg = (const float*)d_in[1];
    const float* w1 = (const float*)d_in[2];
    const float* w2 = (const float*)d_in[3];
    float* out = (float*)d_out;

    cudaFuncSetAttribute(moe_gemm_kernel, cudaFuncAttributeMaxDynamicSharedMemorySize, SMEM_BYTES);

    cudaMemsetAsync(d_out, 0, (size_t)out_size * sizeof(float));
    gate_kernel<<<NTOK/8, 256>>>(x, wg);
    assign_cvt_kernel<<<1 + N1_CHUNKS/1024, 1024>>>(w1);
    moe_gemm_kernel<<<CVT2_TILES + G1_TILES + G2_TILES, 256, SMEM_BYTES>>>(w2, out);
}